// round 2
// baseline (speedup 1.0000x reference)
#include <cuda_runtime.h>

#define BB 2
#define NN 384
#define HID 512
#define RD 256
#define R2 128
#define R4 64
#define NH 8
#define ROWS (BB*NN)              // 768
#define TJ 32
#define TILES (ROWS*(NN/TJ))      // 9216

// ---------------- scratch (no allocations allowed) ----------------
__device__ float g_q[ROWS*RD];
__device__ float g_k[ROWS*RD];
__device__ float g_v[ROWS*HID];
__device__ float g_att[(size_t)ROWS*NN*NH];
__device__ float g_out1[ROWS*HID];

__device__ __forceinline__ float warp_sum(float v){
  #pragma unroll
  for (int o=16;o;o>>=1) v += __shfl_xor_sync(0xffffffffu, v, o);
  return v;
}

// ---------------- kernel A: x = relu(LN(node)); q,k,v projections ----------------
__global__ void __launch_bounds__(256) kA(const float* __restrict__ node,
    const float* __restrict__ g0, const float* __restrict__ b0,
    const float* __restrict__ Wq, const float* __restrict__ bq,
    const float* __restrict__ Wk, const float* __restrict__ bk,
    const float* __restrict__ Wv, const float* __restrict__ bv)
{
  __shared__ float xs[8][HID];
  int tid = threadIdx.x, w = tid>>5, lane = tid&31;
  int r0 = blockIdx.x*8;
  {
    const float* np = node + (size_t)(r0+w)*HID;
    float vals[16]; float s=0.f, q2=0.f;
    #pragma unroll
    for (int u=0;u<16;++u){ float v = np[lane+32*u]; vals[u]=v; s+=v; q2+=v*v; }
    s = warp_sum(s); q2 = warp_sum(q2);
    float m = s*(1.f/HID);
    float rstd = rsqrtf(q2*(1.f/HID) - m*m + 1e-5f);
    #pragma unroll
    for (int u=0;u<16;++u){ int c = lane+32*u; xs[w][c] = fmaxf((vals[u]-m)*rstd*g0[c]+b0[c], 0.f); }
  }
  __syncthreads();
  float aq[8], ak[8], av0[8], av1[8];
  #pragma unroll
  for (int rr=0;rr<8;++rr){aq[rr]=0.f;ak[rr]=0.f;av0[rr]=0.f;av1[rr]=0.f;}
  #pragma unroll 4
  for (int h=0; h<HID; ++h){
    float wq = Wq[h*RD+tid], wk = Wk[h*RD+tid];
    float wv0 = Wv[h*HID+tid], wv1 = Wv[h*HID+tid+256];
    #pragma unroll
    for (int rr=0;rr<8;++rr){
      float x = xs[rr][h];
      aq[rr] += x*wq; ak[rr] += x*wk; av0[rr] += x*wv0; av1[rr] += x*wv1;
    }
  }
  #pragma unroll
  for (int rr=0;rr<8;++rr){
    g_q[(r0+rr)*RD+tid]  = aq[rr]+bq[tid];
    g_k[(r0+rr)*RD+tid]  = ak[rr]+bk[tid];
    g_v[(r0+rr)*HID+tid]      = av0[rr]+bv[tid];
    g_v[(r0+rr)*HID+tid+256]  = av1[rr]+bv[tid+256];
  }
}

// ---------------- kernel B: the pair-MLP (dominant) ----------------
// CTA = 256 threads, TJ=32 pairs per tile, weights persistent in smem.
#define NTB 256
__global__ void __launch_bounds__(256) kB(
    const float* __restrict__ edge, const float* __restrict__ lrel_in,
    const int* __restrict__ drctn, const float* __restrict__ rmask,
    const float* __restrict__ ln1g, const float* __restrict__ ln1b,
    const float* __restrict__ W1, const float* __restrict__ b1,
    const float* __restrict__ ln2g, const float* __restrict__ ln2b,
    const float* __restrict__ W2, const float* __restrict__ b2,
    const float* __restrict__ dirW,
    const float* __restrict__ ln3g, const float* __restrict__ ln3b,
    const float* __restrict__ W3, const float* __restrict__ b3,
    float* __restrict__ lrel_out)
{
  extern __shared__ float sm[];
  float* W1s = sm;                 // 32768
  float* W2s = W1s + 32768;        // 8192
  float* W3s = W2s + 8192;         // 512
  float* dirs = W3s + 512;         // 768
  float* l1g = dirs + 768;         // 256
  float* l1b = l1g + 256;          // 256
  float* b1s = l1b + 256;          // 128
  float* l2g = b1s + 128;          // 128
  float* l2b = l2g + 128;          // 128
  float* b2s = l2b + 128;          // 64
  float* l3g = b2s + 64;           // 64
  float* l3b = l3g + 64;           // 64
  float* b3s = l3b + 64;           // 8
  float* qs  = b3s + 8;            // 256
  float* mm  = qs + 256;           // 32
  float* rs  = mm + 32;            // 32
  int*   dj  = (int*)(rs + 32);    // 32
  float* rel = (float*)(dj + 32);  // 8192 (reused as lr / a3 later)
  float* h1  = rel + 8192;         // 4096
  // total = 55976 floats = 223904 B

  int tid = threadIdx.x;
  for (int i=tid; i<32768; i+=NTB) W1s[i]=W1[i];
  for (int i=tid; i<8192;  i+=NTB) W2s[i]=W2[i];
  for (int i=tid; i<512;   i+=NTB) W3s[i]=W3[i];
  for (int i=tid; i<768;   i+=NTB) dirs[i]=dirW[i];
  if (tid<256){ l1g[tid]=ln1g[tid]; l1b[tid]=ln1b[tid]; }
  if (tid<128){ b1s[tid]=b1[tid]; l2g[tid]=ln2g[tid]; l2b[tid]=ln2b[tid]; }
  if (tid<64){  b2s[tid]=b2[tid]; l3g[tid]=ln3g[tid]; l3b[tid]=ln3b[tid]; }
  if (tid<8)    b3s[tid]=b3[tid];

  int w = tid>>5, lane = tid&31;
  for (int tl = blockIdx.x; tl < TILES; tl += gridDim.x){
    int bi = tl/(NN/TJ);
    int j0 = (tl%(NN/TJ))*TJ;
    int brow = (bi/NN)*NN;
    __syncthreads();                       // also covers initial weight load
    qs[tid] = g_q[bi*RD+tid];
    if (tid<TJ) dj[tid] = drctn[(size_t)bi*NN + j0 + tid];
    __syncthreads();

    // phase 1: rel = q_i * k_j + edge + dir_emb[d]
    {
      float qv = qs[tid];
      #pragma unroll 4
      for (int t=0;t<TJ;++t){
        int j = j0+t;
        float kv = g_k[(brow+j)*RD + tid];
        float ev = edge[((size_t)bi*NN + j)*RD + tid];
        float dv = dirs[dj[t]*RD + tid];
        rel[t*RD + tid] = qv*kv + ev + dv;
      }
    }
    __syncthreads();

    // LN1 stats (warp w handles pairs 4w..4w+3)
    #pragma unroll
    for (int p=0;p<4;++p){
      int t = 4*w+p;
      float s=0.f,q2=0.f;
      #pragma unroll
      for (int u=0;u<8;++u){ float v = rel[t*RD + lane+32*u]; s+=v; q2+=v*v; }
      s=warp_sum(s); q2=warp_sum(q2);
      if (lane==0){ float m=s*(1.f/RD); mm[t]=m; rs[t]=rsqrtf(q2*(1.f/RD)-m*m+1e-5f); }
    }
    __syncthreads();
    #pragma unroll 4
    for (int idx=tid; idx<TJ*RD; idx+=NTB){
      int t = idx>>8, r = idx&255;
      rel[idx] = (rel[idx]-mm[t])*rs[t]*l1g[r]+l1b[r];
    }
    __syncthreads();

    // GEMM1: h1 = relu(LNrel @ W1 + b1)   (4 pairs x 4 cols per lane)
    {
      float acc[4][4];
      #pragma unroll
      for (int p=0;p<4;++p){
        #pragma unroll
        for (int c=0;c<4;++c) acc[p][c]=0.f;
      }
      const float* w1p = W1s + 4*lane;
      const float* rp  = rel + (4*w)*RD;
      #pragma unroll 2
      for (int r=0;r<RD;++r){
        float4 wv = *(const float4*)(w1p + r*R2);
        #pragma unroll
        for (int p=0;p<4;++p){
          float a = rp[p*RD + r];
          acc[p][0]+=a*wv.x; acc[p][1]+=a*wv.y; acc[p][2]+=a*wv.z; acc[p][3]+=a*wv.w;
        }
      }
      int c0 = 4*lane;
      #pragma unroll
      for (int p=0;p<4;++p){
        float4 o;
        o.x=fmaxf(acc[p][0]+b1s[c0],0.f);
        o.y=fmaxf(acc[p][1]+b1s[c0+1],0.f);
        o.z=fmaxf(acc[p][2]+b1s[c0+2],0.f);
        o.w=fmaxf(acc[p][3]+b1s[c0+3],0.f);
        *(float4*)(h1 + (4*w+p)*R2 + c0) = o;
      }
    }
    __syncthreads();

    // LN2 stats + normalize in place
    #pragma unroll
    for (int p=0;p<4;++p){
      int t=4*w+p;
      float s=0.f,q2=0.f;
      #pragma unroll
      for (int u=0;u<4;++u){ float v=h1[t*R2+lane+32*u]; s+=v; q2+=v*v; }
      s=warp_sum(s); q2=warp_sum(q2);
      if (lane==0){ float m=s*(1.f/R2); mm[t]=m; rs[t]=rsqrtf(q2*(1.f/R2)-m*m+1e-5f); }
    }
    __syncthreads();
    #pragma unroll 4
    for (int idx=tid; idx<TJ*R2; idx+=NTB){
      int t=idx>>7, r=idx&127;
      h1[idx]=(h1[idx]-mm[t])*rs[t]*l2g[r]+l2b[r];
    }
    __syncthreads();

    // GEMM2 + add last_relation -> write last_rel output; keep in smem (aliases rel)
    float* lr = rel;
    {
      float acc[4][2];
      #pragma unroll
      for (int p=0;p<4;++p){acc[p][0]=0.f;acc[p][1]=0.f;}
      const float* w2p = W2s + 2*lane;
      const float* hp  = h1 + (4*w)*R2;
      #pragma unroll 2
      for (int r=0;r<R2;++r){
        float2 wv = *(const float2*)(w2p + r*R4);
        #pragma unroll
        for (int p=0;p<4;++p){
          float a = hp[p*R2 + r];
          acc[p][0]+=a*wv.x; acc[p][1]+=a*wv.y;
        }
      }
      int c0=2*lane;
      #pragma unroll
      for (int p=0;p<4;++p){
        int t=4*w+p; int j=j0+t;
        size_t base = ((size_t)bi*NN + j)*R4 + c0;
        float2 o;
        o.x = acc[p][0]+b2s[c0]  +lrel_in[base];
        o.y = acc[p][1]+b2s[c0+1]+lrel_in[base+1];
        *(float2*)(lrel_out + base) = o;
        lr[t*R4+c0]=o.x; lr[t*R4+c0+1]=o.y;
      }
    }
    __syncthreads();

    // LN3 on relu(last_rel)
    #pragma unroll
    for (int p=0;p<4;++p){
      int t=4*w+p;
      float v0=fmaxf(lr[t*R4+lane],0.f), v1=fmaxf(lr[t*R4+lane+32],0.f);
      float s=warp_sum(v0+v1), q2=warp_sum(v0*v0+v1*v1);
      if (lane==0){ float m=s*(1.f/R4); mm[t]=m; rs[t]=rsqrtf(q2*(1.f/R4)-m*m+1e-5f); }
    }
    __syncthreads();
    float* a3 = rel + TJ*R4;   // second half of rel buffer
    #pragma unroll
    for (int idx=tid; idx<TJ*R4; idx+=NTB){
      int t=idx>>6, r=idx&63;
      float v=fmaxf(lr[idx],0.f);
      a3[idx]=(v-mm[t])*rs[t]*l3g[r]+l3b[r];
    }
    __syncthreads();

    // logits: att = a3 @ W3 + b3 + rel_mask  (1 output per thread)
    {
      int t = tid>>3, hh = tid&7;
      float acc=0.f;
      const float* ap = a3 + t*R4;
      #pragma unroll 8
      for (int r=0;r<R4;++r) acc += ap[r]*W3s[r*NH+hh];
      int j=j0+t;
      size_t ib = ((size_t)bi*NN+j)*NH + hh;
      g_att[ib] = acc + b3s[hh] + rmask[ib];
    }
  }
}

// ---------------- kernel C: softmax over j ----------------
__global__ void __launch_bounds__(256) kC()
{
  __shared__ float s[NN*NH];
  int bi = blockIdx.x, tid=threadIdx.x;
  float* g = g_att + (size_t)bi*NN*NH;
  for (int i=tid;i<NN*NH;i+=256) s[i]=g[i];
  __syncthreads();
  int w=tid>>5, lane=tid&31;   // warp w handles head w
  float mx=-3.4e38f;
  float e[12];
  #pragma unroll
  for (int u=0;u<12;++u) mx = fmaxf(mx, s[(lane+32*u)*NH + w]);
  #pragma unroll
  for (int o=16;o;o>>=1) mx = fmaxf(mx, __shfl_xor_sync(0xffffffffu,mx,o));
  float sum=0.f;
  #pragma unroll
  for (int u=0;u<12;++u){ e[u]=__expf(s[(lane+32*u)*NH+w]-mx); sum+=e[u]; }
  sum = warp_sum(sum);
  float inv = 1.f/sum;
  #pragma unroll
  for (int u=0;u<12;++u) s[(lane+32*u)*NH+w] = e[u]*inv;
  __syncthreads();
  for (int i=tid;i<NN*NH;i+=256) g[i]=s[i];
}

// ---------------- kernel D: out1[b,i,h,d] = sum_j att * v ----------------
__global__ void __launch_bounds__(256) kD()
{
  __shared__ float as[4][64*NH];
  int tid=threadIdx.x;
  int row0 = blockIdx.x*4;
  int b = row0/NN;
  int h0 = tid>>6;
  float acc0[4], acc1[4];
  #pragma unroll
  for (int rr=0;rr<4;++rr){acc0[rr]=0.f;acc1[rr]=0.f;}
  for (int jc=0;jc<NN/64;++jc){
    __syncthreads();
    for (int idx=tid; idx<4*64*NH; idx+=256){
      int rr=idx>>9, rest=idx&511;
      as[rr][rest] = g_att[((size_t)(row0+rr)*NN + jc*64)*NH + rest];
    }
    __syncthreads();
    #pragma unroll 2
    for (int jj=0;jj<64;++jj){
      const float* vp = g_v + (size_t)(b*NN + jc*64+jj)*HID;
      float v0=vp[tid], v1=vp[tid+256];
      #pragma unroll
      for (int rr=0;rr<4;++rr){
        acc0[rr]+=as[rr][jj*NH+h0]*v0;
        acc1[rr]+=as[rr][jj*NH+h0+4]*v1;
      }
    }
  }
  #pragma unroll
  for (int rr=0;rr<4;++rr){
    g_out1[(row0+rr)*HID + tid]     = acc0[rr];
    g_out1[(row0+rr)*HID + tid+256] = acc1[rr];
  }
}

// ---------------- kernel E: out = out1 @ Wo + bo ----------------
__global__ void __launch_bounds__(256) kE(const float* __restrict__ Wo,
                                          const float* __restrict__ bo,
                                          float* __restrict__ out)
{
  __shared__ float ys[8][HID];
  int tid=threadIdx.x; int r0=blockIdx.x*8;
  for (int idx=tid; idx<8*HID; idx+=256) ys[idx>>9][idx&511] = g_out1[(size_t)r0*HID + idx];
  __syncthreads();
  float a0[8],a1[8];
  #pragma unroll
  for (int rr=0;rr<8;++rr){a0[rr]=0.f;a1[rr]=0.f;}
  #pragma unroll 4
  for (int h=0;h<HID;++h){
    float w0=Wo[h*HID+tid], w1=Wo[h*HID+tid+256];
    #pragma unroll
    for (int rr=0;rr<8;++rr){ float x=ys[rr][h]; a0[rr]+=x*w0; a1[rr]+=x*w1; }
  }
  #pragma unroll
  for (int rr=0;rr<8;++rr){
    out[(r0+rr)*HID+tid]     = a0[rr]+bo[tid];
    out[(r0+rr)*HID+tid+256] = a1[rr]+bo[tid+256];
  }
}

// ---------------- launch ----------------
extern "C" void kernel_launch(void* const* d_in, const int* in_sizes, int n_in,
                              void* d_out, int out_size)
{
  const float* node        = (const float*)d_in[0];
  const float* edge        = (const float*)d_in[1];
  const float* last_rel_in = (const float*)d_in[2];
  const int* drctn         = (const int*)d_in[3];   // jax int64 w/o x64 => int32
  const float* rel_mask    = (const float*)d_in[4];
  const float* ln0_g=(const float*)d_in[5];  const float* ln0_b=(const float*)d_in[6];
  const float* Wq=(const float*)d_in[7];     const float* bq=(const float*)d_in[8];
  const float* Wk=(const float*)d_in[9];     const float* bk=(const float*)d_in[10];
  const float* Wv=(const float*)d_in[11];    const float* bv=(const float*)d_in[12];
  const float* ln1_g=(const float*)d_in[13]; const float* ln1_b=(const float*)d_in[14];
  const float* W1=(const float*)d_in[15];    const float* b1=(const float*)d_in[16];
  const float* ln2_g=(const float*)d_in[17]; const float* ln2_b=(const float*)d_in[18];
  const float* W2=(const float*)d_in[19];    const float* b2=(const float*)d_in[20];
  const float* dir_emb=(const float*)d_in[21];
  const float* ln3_g=(const float*)d_in[22]; const float* ln3_b=(const float*)d_in[23];
  const float* W3=(const float*)d_in[24];    const float* b3=(const float*)d_in[25];
  const float* Wo=(const float*)d_in[26];    const float* bo=(const float*)d_in[27];

  float* out = (float*)d_out;                      // [B,N,HID] first
  // place last_rel at the END of the output buffer: always in-bounds.
  const size_t LRELN = (size_t)BB*NN*NN*R4;        // 18,874,368
  float* lrel_out = out + ((size_t)out_size - LRELN);

  kA<<<ROWS/8,256>>>(node, ln0_g, ln0_b, Wq,bq,Wk,bk,Wv,bv);

  const int SMEM_B = 55976*4;  // 223904 bytes
  cudaFuncSetAttribute(kB, cudaFuncAttributeMaxDynamicSharedMemorySize, SMEM_B);
  kB<<<304,256,SMEM_B>>>(edge, last_rel_in, drctn, rel_mask,
                         ln1_g, ln1_b, W1, b1, ln2_g, ln2_b, W2, b2,
                         dir_emb, ln3_g, ln3_b, W3, b3, lrel_out);

  kC<<<ROWS,256>>>();
  kD<<<ROWS/4,256>>>();
  kE<<<ROWS/8,256>>>(Wo, bo, out);
}

// round 3
// speedup vs baseline: 1.5577x; 1.5577x over previous
#include <cuda_runtime.h>

#define BB 2
#define NN 384
#define HID 512
#define RD 256
#define R2 128
#define R4 64
#define NH 8
#define ROWS (BB*NN)              // 768
#define TJ 32
#define TILES (ROWS*(NN/TJ))      // 9216

// ---------------- scratch ----------------
__device__ float g_q[ROWS*RD];
__device__ float g_k[ROWS*RD];
__device__ float g_v[ROWS*HID];
__device__ float g_att[(size_t)ROWS*NN*NH];
__device__ float g_out1p[4][ROWS*HID];

__device__ __forceinline__ float warp_sum(float v){
  #pragma unroll
  for (int o=16;o;o>>=1) v += __shfl_xor_sync(0xffffffffu, v, o);
  return v;
}
// packed f32x2 helpers (sm_103a FFMA2 path)
__device__ __forceinline__ unsigned long long fma2(unsigned long long a, unsigned long long b, unsigned long long c){
  unsigned long long d;
  asm("fma.rn.f32x2 %0, %1, %2, %3;" : "=l"(d) : "l"(a), "l"(b), "l"(c));
  return d;
}
__device__ __forceinline__ unsigned long long pack2(float x){
  unsigned long long d;
  asm("mov.b64 %0, {%1, %1};" : "=l"(d) : "f"(x));
  return d;
}
__device__ __forceinline__ float lo2(unsigned long long v){ return __uint_as_float((unsigned)v); }
__device__ __forceinline__ float hi2(unsigned long long v){ return __uint_as_float((unsigned)(v>>32)); }

// ---------------- kernel A ----------------
__global__ void __launch_bounds__(256) kA(const float* __restrict__ node,
    const float* __restrict__ g0, const float* __restrict__ b0,
    const float* __restrict__ Wq, const float* __restrict__ bq,
    const float* __restrict__ Wk, const float* __restrict__ bk,
    const float* __restrict__ Wv, const float* __restrict__ bv)
{
  __shared__ float xs[8][HID];
  int tid = threadIdx.x, w = tid>>5, lane = tid&31;
  int r0 = blockIdx.x*8;
  {
    const float* np = node + (size_t)(r0+w)*HID;
    float vals[16]; float s=0.f, q2=0.f;
    #pragma unroll
    for (int u=0;u<16;++u){ float v = np[lane+32*u]; vals[u]=v; s+=v; q2+=v*v; }
    s = warp_sum(s); q2 = warp_sum(q2);
    float m = s*(1.f/HID);
    float rstd = rsqrtf(q2*(1.f/HID) - m*m + 1e-5f);
    #pragma unroll
    for (int u=0;u<16;++u){ int c = lane+32*u; xs[w][c] = fmaxf((vals[u]-m)*rstd*g0[c]+b0[c], 0.f); }
  }
  __syncthreads();
  float aq[8], ak[8], av0[8], av1[8];
  #pragma unroll
  for (int rr=0;rr<8;++rr){aq[rr]=0.f;ak[rr]=0.f;av0[rr]=0.f;av1[rr]=0.f;}
  #pragma unroll 4
  for (int h=0; h<HID; ++h){
    float wq = Wq[h*RD+tid], wk = Wk[h*RD+tid];
    float wv0 = Wv[h*HID+tid], wv1 = Wv[h*HID+tid+256];
    #pragma unroll
    for (int rr=0;rr<8;++rr){
      float x = xs[rr][h];
      aq[rr] += x*wq; ak[rr] += x*wk; av0[rr] += x*wv0; av1[rr] += x*wv1;
    }
  }
  #pragma unroll
  for (int rr=0;rr<8;++rr){
    g_q[(r0+rr)*RD+tid]  = aq[rr]+bq[tid];
    g_k[(r0+rr)*RD+tid]  = ak[rr]+bk[tid];
    g_v[(r0+rr)*HID+tid]      = av0[rr]+bv[tid];
    g_v[(r0+rr)*HID+tid+256]  = av1[rr]+bv[tid+256];
  }
}

// ---------------- kernel B: pair-MLP, 512 threads, fma2 + split-K ----------------
#define NTB 512
__global__ void __launch_bounds__(512) kB(
    const float* __restrict__ edge, const float* __restrict__ lrel_in,
    const int* __restrict__ drctn, const float* __restrict__ rmask,
    const float* __restrict__ ln1g, const float* __restrict__ ln1b,
    const float* __restrict__ W1, const float* __restrict__ b1,
    const float* __restrict__ ln2g, const float* __restrict__ ln2b,
    const float* __restrict__ W2, const float* __restrict__ b2,
    const float* __restrict__ dirW,
    const float* __restrict__ ln3g, const float* __restrict__ ln3b,
    const float* __restrict__ W3, const float* __restrict__ b3,
    float* __restrict__ lrel_out)
{
  extern __shared__ float sm[];
  float* W1s = sm;                 // 32768
  float* W2s = W1s + 32768;        // 8192
  float* W3s = W2s + 8192;         // 512
  float* dirs = W3s + 512;         // 768
  float* l1g = dirs + 768;         // 256
  float* l1b = l1g + 256;          // 256
  float* b1s = l1b + 256;          // 128
  float* l2g = b1s + 128;          // 128
  float* l2b = l2g + 128;          // 128
  float* b2s = l2b + 128;          // 64
  float* l3g = b2s + 64;           // 64
  float* l3b = l3g + 64;           // 64
  float* b3s = l3b + 64;           // 8
  float* qs  = b3s + 8;            // 256
  float* mm  = qs + 256;           // 32
  float* rs  = mm + 32;            // 32
  int*   dj  = (int*)(rs + 32);    // 32
  float* rel = (float*)(dj + 32);  // 8192
  float* h1  = rel + 8192;         // 4096
  // total 55976 floats = 223904 B

  int tid = threadIdx.x;
  for (int i=tid; i<32768; i+=NTB) W1s[i]=W1[i];
  for (int i=tid; i<8192;  i+=NTB) W2s[i]=W2[i];
  for (int i=tid; i<512;   i+=NTB) W3s[i]=W3[i];
  for (int i=tid; i<768;   i+=NTB) dirs[i]=dirW[i];
  if (tid<256){ l1g[tid]=ln1g[tid]; l1b[tid]=ln1b[tid]; }
  if (tid<128){ b1s[tid]=b1[tid]; l2g[tid]=ln2g[tid]; l2b[tid]=ln2b[tid]; }
  if (tid<64){  b2s[tid]=b2[tid]; l3g[tid]=ln3g[tid]; l3b[tid]=ln3b[tid]; }
  if (tid<8)    b3s[tid]=b3[tid];

  int w = tid>>5, lane = tid&31;
  int og = w>>1, ks = w&1;             // 8 output groups x 2 K-splits

  for (int tl = blockIdx.x; tl < TILES; tl += gridDim.x){
    int bi = tl/(NN/TJ);
    int j0 = (tl%(NN/TJ))*TJ;
    int brow = (bi/NN)*NN;
    __syncthreads();
    if (tid<256) qs[tid] = g_q[bi*RD+tid];
    if (tid<TJ) dj[tid] = drctn[(size_t)bi*NN + j0 + tid];
    __syncthreads();

    // phase 1: rel = q_i * k_j + edge + dir_emb[d]
    {
      int half = tid>>8, c = tid&255;
      float qv = qs[c];
      #pragma unroll 4
      for (int t0=0;t0<16;++t0){
        int t = half*16 + t0;
        int j = j0+t;
        float kv = g_k[(brow+j)*RD + c];
        float ev = edge[((size_t)bi*NN + j)*RD + c];
        float dv = dirs[dj[t]*RD + c];
        rel[t*RD + c] = qv*kv + ev + dv;
      }
    }
    __syncthreads();

    // LN1 stats (warp w handles pairs 2w,2w+1)
    #pragma unroll
    for (int p=0;p<2;++p){
      int t = 2*w+p;
      float s=0.f,q2=0.f;
      #pragma unroll
      for (int u=0;u<8;++u){ float v = rel[t*RD + lane+32*u]; s+=v; q2+=v*v; }
      s=warp_sum(s); q2=warp_sum(q2);
      if (lane==0){ float m=s*(1.f/RD); mm[t]=m; rs[t]=rsqrtf(q2*(1.f/RD)-m*m+1e-5f); }
    }
    __syncthreads();
    #pragma unroll 4
    for (int idx=tid; idx<TJ*RD; idx+=NTB){
      int t = idx>>8, r = idx&255;
      rel[idx] = (rel[idx]-mm[t])*rs[t]*l1g[r]+l1b[r];
    }
    __syncthreads();

    // GEMM1: h1 = relu(LNrel @ W1 + b1).
    // warp tile = 4 pairs x 128 cols, split-K across warp pairs (ks).
    {
      unsigned long long acc[4][2];
      #pragma unroll
      for (int p=0;p<4;++p){ acc[p][0]=0ull; acc[p][1]=0ull; }
      int rbase = ks*128;
      const float* rp = rel + (4*og)*RD;
      #pragma unroll 2
      for (int rb=rbase; rb<rbase+128; rb+=4){
        float a4[4][4];
        #pragma unroll
        for (int p=0;p<4;++p) *(float4*)a4[p] = *(const float4*)(rp + p*RD + rb);
        #pragma unroll
        for (int k=0;k<4;++k){
          ulonglong2 wv = *(const ulonglong2*)(W1s + (rb+k)*R2 + 4*lane);
          #pragma unroll
          for (int p=0;p<4;++p){
            unsigned long long a = pack2(a4[p][k]);
            acc[p][0] = fma2(a, wv.x, acc[p][0]);
            acc[p][1] = fma2(a, wv.y, acc[p][1]);
          }
        }
      }
      // ks=1 warps publish partials into h1, ks=0 warps finish
      if (ks==1){
        #pragma unroll
        for (int p=0;p<4;++p){
          ulonglong2 v; v.x=acc[p][0]; v.y=acc[p][1];
          *(ulonglong2*)(h1 + (4*og+p)*R2 + 4*lane) = v;
        }
      }
      __syncthreads();
      if (ks==0){
        int c0=4*lane;
        #pragma unroll
        for (int p=0;p<4;++p){
          int t=4*og+p;
          float4 part = *(const float4*)(h1 + t*R2 + c0);
          float4 o;
          o.x=fmaxf(lo2(acc[p][0])+part.x+b1s[c0  ],0.f);
          o.y=fmaxf(hi2(acc[p][0])+part.y+b1s[c0+1],0.f);
          o.z=fmaxf(lo2(acc[p][1])+part.z+b1s[c0+2],0.f);
          o.w=fmaxf(hi2(acc[p][1])+part.w+b1s[c0+3],0.f);
          *(float4*)(h1 + t*R2 + c0) = o;
        }
      }
    }
    __syncthreads();

    // LN2 stats + normalize in place
    #pragma unroll
    for (int p=0;p<2;++p){
      int t=2*w+p;
      float s=0.f,q2=0.f;
      #pragma unroll
      for (int u=0;u<4;++u){ float v=h1[t*R2+lane+32*u]; s+=v; q2+=v*v; }
      s=warp_sum(s); q2=warp_sum(q2);
      if (lane==0){ float m=s*(1.f/R2); mm[t]=m; rs[t]=rsqrtf(q2*(1.f/R2)-m*m+1e-5f); }
    }
    __syncthreads();
    #pragma unroll 4
    for (int idx=tid; idx<TJ*R2; idx+=NTB){
      int t=idx>>7, r=idx&127;
      h1[idx]=(h1[idx]-mm[t])*rs[t]*l2g[r]+l2b[r];
    }
    __syncthreads();

    // GEMM2 + add last_relation; warp tile = 4 pairs x 64 cols, split-K.
    float* lr = rel;            // [0,2048): last_rel tile
    float* g2s = rel + 4096;    // GEMM2 partial scratch (2048 floats)
    {
      unsigned long long acc[4];
      #pragma unroll
      for (int p=0;p<4;++p) acc[p]=0ull;
      int rbase = ks*64;
      const float* hp = h1 + (4*og)*R2;
      #pragma unroll 2
      for (int rb=rbase; rb<rbase+64; rb+=4){
        float a4[4][4];
        #pragma unroll
        for (int p=0;p<4;++p) *(float4*)a4[p] = *(const float4*)(hp + p*R2 + rb);
        #pragma unroll
        for (int k=0;k<4;++k){
          unsigned long long wv = *(const unsigned long long*)(W2s + (rb+k)*R4 + 2*lane);
          #pragma unroll
          for (int p=0;p<4;++p) acc[p] = fma2(pack2(a4[p][k]), wv, acc[p]);
        }
      }
      if (ks==1){
        #pragma unroll
        for (int p=0;p<4;++p)
          *(unsigned long long*)(g2s + (4*og+p)*R4 + 2*lane) = acc[p];
      }
      __syncthreads();
      if (ks==0){
        int c0=2*lane;
        #pragma unroll
        for (int p=0;p<4;++p){
          int t=4*og+p; int j=j0+t;
          unsigned long long part = *(const unsigned long long*)(g2s + t*R4 + c0);
          size_t base = ((size_t)bi*NN + j)*R4 + c0;
          float2 lrin = *(const float2*)(lrel_in+base);
          float2 o;
          o.x = lo2(acc[p])+lo2(part)+b2s[c0]  +lrin.x;
          o.y = hi2(acc[p])+hi2(part)+b2s[c0+1]+lrin.y;
          *(float2*)(lrel_out + base) = o;
          lr[t*R4+c0]=o.x; lr[t*R4+c0+1]=o.y;
        }
      }
    }
    __syncthreads();

    // LN3 on relu(last_rel)
    #pragma unroll
    for (int p=0;p<2;++p){
      int t=2*w+p;
      float v0=fmaxf(lr[t*R4+lane],0.f), v1=fmaxf(lr[t*R4+lane+32],0.f);
      float s=warp_sum(v0+v1), q2=warp_sum(v0*v0+v1*v1);
      if (lane==0){ float m=s*(1.f/R4); mm[t]=m; rs[t]=rsqrtf(q2*(1.f/R4)-m*m+1e-5f); }
    }
    __syncthreads();
    float* a3 = rel + TJ*R4;   // [2048,4096)
    #pragma unroll
    for (int idx=tid; idx<TJ*R4; idx+=NTB){
      int t=idx>>6, r=idx&63;
      float v=fmaxf(lr[idx],0.f);
      a3[idx]=(v-mm[t])*rs[t]*l3g[r]+l3b[r];
    }
    __syncthreads();

    // logits
    if (tid < 256){
      int t = tid>>3, hh = tid&7;
      float acc=0.f;
      const float* ap = a3 + t*R4;
      #pragma unroll 8
      for (int r=0;r<R4;++r) acc += ap[r]*W3s[r*NH+hh];
      int j=j0+t;
      size_t ib = ((size_t)bi*NN+j)*NH + hh;
      g_att[ib] = acc + b3s[hh] + rmask[ib];
    }
  }
}

// ---------------- kernel C: softmax over j ----------------
__global__ void __launch_bounds__(256) kC()
{
  __shared__ float s[NN*NH];
  int bi = blockIdx.x, tid=threadIdx.x;
  float* g = g_att + (size_t)bi*NN*NH;
  for (int i=tid;i<NN*NH;i+=256) s[i]=g[i];
  __syncthreads();
  int w=tid>>5, lane=tid&31;
  float mx=-3.4e38f;
  float e[12];
  #pragma unroll
  for (int u=0;u<12;++u) mx = fmaxf(mx, s[(lane+32*u)*NH + w]);
  #pragma unroll
  for (int o=16;o;o>>=1) mx = fmaxf(mx, __shfl_xor_sync(0xffffffffu,mx,o));
  float sum=0.f;
  #pragma unroll
  for (int u=0;u<12;++u){ e[u]=__expf(s[(lane+32*u)*NH+w]-mx); sum+=e[u]; }
  sum = warp_sum(sum);
  float inv = 1.f/sum;
  #pragma unroll
  for (int u=0;u<12;++u) s[(lane+32*u)*NH+w] = e[u]*inv;
  __syncthreads();
  for (int i=tid;i<NN*NH;i+=256) g[i]=s[i];
}

// ---------------- kernel D: partial attn*V over j-splits ----------------
__global__ void __launch_bounds__(256) kD()
{
  __shared__ float as[4][32*NH];
  int tid=threadIdx.x;
  int row0 = blockIdx.x*4;
  int js = blockIdx.y;
  int b = row0/NN;
  int h0 = tid>>6;
  float acc0[4], acc1[4];
  #pragma unroll
  for (int rr=0;rr<4;++rr){acc0[rr]=0.f;acc1[rr]=0.f;}
  for (int jc=0;jc<3;++jc){
    int jb = js*96 + jc*32;
    __syncthreads();
    for (int idx=tid; idx<4*32*NH; idx+=256){
      int rr=idx>>8, rest=idx&255;
      as[rr][rest] = g_att[((size_t)(row0+rr)*NN + jb)*NH + rest];
    }
    __syncthreads();
    #pragma unroll 4
    for (int jj=0;jj<32;++jj){
      const float* vp = g_v + (size_t)(b*NN + jb+jj)*HID;
      float v0=vp[tid], v1=vp[tid+256];
      #pragma unroll
      for (int rr=0;rr<4;++rr){
        acc0[rr]+=as[rr][jj*NH+h0]*v0;
        acc1[rr]+=as[rr][jj*NH+h0+4]*v1;
      }
    }
  }
  #pragma unroll
  for (int rr=0;rr<4;++rr){
    g_out1p[js][(row0+rr)*HID + tid]     = acc0[rr];
    g_out1p[js][(row0+rr)*HID + tid+256] = acc1[rr];
  }
}

// ---------------- kernel E: out = (sum_js out1p) @ Wo + bo ----------------
__global__ void __launch_bounds__(256) kE(const float* __restrict__ Wo,
                                          const float* __restrict__ bo,
                                          float* __restrict__ out)
{
  __shared__ float ys[8][HID];
  int tid=threadIdx.x; int r0=blockIdx.x*8;
  for (int idx=tid; idx<8*HID; idx+=256){
    size_t base=(size_t)r0*HID+idx;
    ys[idx>>9][idx&511] = g_out1p[0][base]+g_out1p[1][base]+g_out1p[2][base]+g_out1p[3][base];
  }
  __syncthreads();
  float a0[8],a1[8];
  #pragma unroll
  for (int rr=0;rr<8;++rr){a0[rr]=0.f;a1[rr]=0.f;}
  #pragma unroll 4
  for (int h=0;h<HID;++h){
    float w0=Wo[h*HID+tid], w1=Wo[h*HID+tid+256];
    #pragma unroll
    for (int rr=0;rr<8;++rr){ float x=ys[rr][h]; a0[rr]+=x*w0; a1[rr]+=x*w1; }
  }
  #pragma unroll
  for (int rr=0;rr<8;++rr){
    out[(r0+rr)*HID+tid]     = a0[rr]+bo[tid];
    out[(r0+rr)*HID+tid+256] = a1[rr]+bo[tid+256];
  }
}

// ---------------- launch ----------------
extern "C" void kernel_launch(void* const* d_in, const int* in_sizes, int n_in,
                              void* d_out, int out_size)
{
  const float* node        = (const float*)d_in[0];
  const float* edge        = (const float*)d_in[1];
  const float* last_rel_in = (const float*)d_in[2];
  const int* drctn         = (const int*)d_in[3];
  const float* rel_mask    = (const float*)d_in[4];
  const float* ln0_g=(const float*)d_in[5];  const float* ln0_b=(const float*)d_in[6];
  const float* Wq=(const float*)d_in[7];     const float* bq=(const float*)d_in[8];
  const float* Wk=(const float*)d_in[9];     const float* bk=(const float*)d_in[10];
  const float* Wv=(const float*)d_in[11];    const float* bv=(const float*)d_in[12];
  const float* ln1_g=(const float*)d_in[13]; const float* ln1_b=(const float*)d_in[14];
  const float* W1=(const float*)d_in[15];    const float* b1=(const float*)d_in[16];
  const float* ln2_g=(const float*)d_in[17]; const float* ln2_b=(const float*)d_in[18];
  const float* W2=(const float*)d_in[19];    const float* b2=(const float*)d_in[20];
  const float* dir_emb=(const float*)d_in[21];
  const float* ln3_g=(const float*)d_in[22]; const float* ln3_b=(const float*)d_in[23];
  const float* W3=(const float*)d_in[24];    const float* b3=(const float*)d_in[25];
  const float* Wo=(const float*)d_in[26];    const float* bo=(const float*)d_in[27];

  float* out = (float*)d_out;
  const size_t LRELN = (size_t)BB*NN*NN*R4;
  float* lrel_out = out + ((size_t)out_size - LRELN);

  kA<<<ROWS/8,256>>>(node, ln0_g, ln0_b, Wq,bq,Wk,bk,Wv,bv);

  const int SMEM_B = 55976*4;
  cudaFuncSetAttribute(kB, cudaFuncAttributeMaxDynamicSharedMemorySize, SMEM_B);
  kB<<<152,512,SMEM_B>>>(edge, last_rel_in, drctn, rel_mask,
                         ln1_g, ln1_b, W1, b1, ln2_g, ln2_b, W2, b2,
                         dir_emb, ln3_g, ln3_b, W3, b3, lrel_out);

  kC<<<ROWS,256>>>();
  kD<<<dim3(192,4),256>>>();
  kE<<<ROWS/8,256>>>(Wo, bo, out);
}